// round 5
// baseline (speedup 1.0000x reference)
#include <cuda_runtime.h>
typedef unsigned long long u64;

#define Bn 16
#define Cn 32
#define Sn 256
#define Mn 12
#define Rn 24
#define Ln 4
#define BCn (Bn*Cn)
#define WTN (Ln*Rn*Mn*Cn*Cn)
#define SS (Sn*Sn)

__device__ float g_h[(size_t)BCn*SS];
__device__ float g_Y[(size_t)BCn*Sn*(2*Mn)];
__device__ float g_T[(size_t)Bn*Sn*Cn*(2*Mn)];
__device__ float g_Wtr[WTN];
__device__ float g_Wti[WTN];
__device__ float g_ch[Rn*Sn];
__device__ float g_sh[Rn*Sn];
__device__ float g_trigH[Rn*128];   // q<12: cos(q w th), q>=12: sin((q-12) w th), w<128
__device__ u64   g_dpk[22*128];     // rows 0-10: {cos(kw), (-1)^k cos(kw)} k=1..11; 11-21: sin

__device__ __forceinline__ u64 pk2(float x, float y) {
    u64 r; asm("mov.b64 %0,{%1,%2};" : "=l"(r) : "f"(x), "f"(y)); return r;
}
__device__ __forceinline__ void up2(u64 a, float& x, float& y) {
    asm("mov.b64 {%0,%1},%2;" : "=f"(x), "=f"(y) : "l"(a));
}
__device__ __forceinline__ u64 f2fma(u64 a, u64 b, u64 c) {
    u64 d; asm("fma.rn.f32x2 %0,%1,%2,%3;" : "=l"(d) : "l"(a), "l"(b), "l"(c)); return d;
}

__global__ void k_setup() {
    int q = blockIdx.x, w = threadIdx.x;
    float s, c;
    int ky = (q < Mn) ? q : 232 + q;
    sincospif((float)((ky*w) & 255) * (2.0f/256.0f), &s, &c);
    g_ch[q*Sn + w] = c;
    g_sh[q*Sn + w] = s;
    if (w < 128) {
        int k = (q < Mn) ? q : q - Mn;
        float s2, c2;
        sincospif((float)((k*w) & 255) * (2.0f/256.0f), &s2, &c2);
        g_trigH[q*128 + w] = (q < Mn) ? c2 : s2;
        if (q >= 1 && q < Mn) {
            float sg = (q & 1) ? -1.f : 1.f;
            g_dpk[(q-1)*128 + w]  = pk2(c2, sg*c2);
            g_dpk[(10+q)*128 + w] = pk2(s2, sg*s2);
        }
    }
}

__global__ void k_wt(const float* __restrict__ w1r, const float* __restrict__ w1i,
                     const float* __restrict__ w2r, const float* __restrict__ w2i) {
    int flat = blockIdx.x*256 + threadIdx.x;
    if (flat >= WTN) return;
    int o = flat & 31;
    int i = (flat >> 5) & 31;
    int k = (flat >> 10) % Mn;
    int r = (flat / (Mn*Cn*Cn)) % Rn;
    int l =  flat / (Rn*Mn*Cn*Cn);
    int ky = (r < Mn) ? r : r - Mn;
    size_t s = ((((size_t)l*Cn + i)*Cn + o)*Mn + ky)*Mn + k;
    const float sc = 1.0f/65536.0f;
    if (r < Mn) { g_Wtr[flat] = w1r[s]*sc; g_Wti[flat] = w1i[s]*sc; }
    else        { g_Wtr[flat] = w2r[s]*sc; g_Wti[flat] = w2i[s]*sc; }
}

// ---- k_modes: identical to round-2 (known good) ----
__global__ void __launch_bounds__(768) k_modes(int l) {
    extern __shared__ float sm[];
    float* sYr = sm;
    float* sYi = sm + Cn*257;
    float* sZr = sm + 2*Cn*257;
    float* sZi = sZr + Cn*25;
    float* sOr = sZi + Cn*25;
    float* sOi = sOr + Cn*25;
    int b = blockIdx.x / Mn, k = blockIdx.x % Mn;
    int t = threadIdx.x;
    for (int idx = t; idx < Cn*Sn; idx += 768) {
        int c = idx >> 8, h = idx & 255;
        const float* yp = g_Y + ((size_t)(b*Cn + c)*Sn + h)*(2*Mn);
        sYr[c*257 + h] = yp[k];
        sYi[c*257 + h] = yp[Mn + k];
    }
    __syncthreads();
    int warp = t >> 5, lane = t & 31;
    {
        int r = warp;
        const float* chp = g_ch + r*Sn;
        const float* shp = g_sh + r*Sn;
        const float* yr = sYr + lane*257;
        const float* yi = sYi + lane*257;
        float zr = 0.f, zi = 0.f;
        #pragma unroll 8
        for (int h = 0; h < Sn; h++) {
            float cv = __ldg(chp + h), sv = __ldg(shp + h);
            float a = yr[h], bb = yi[h];
            zr += a*cv + bb*sv;
            zi += bb*cv - a*sv;
        }
        sZr[lane*25 + r] = zr;
        sZi[lane*25 + r] = zi;
    }
    __syncthreads();
    {
        int r = warp;
        size_t wb = ((size_t)((l*Rn + r)*Mn + k))*(Cn*Cn) + lane;
        const float* wr = g_Wtr + wb;
        const float* wi = g_Wti + wb;
        float orr = 0.f, oii = 0.f;
        #pragma unroll 8
        for (int i = 0; i < Cn; i++) {
            float zr = sZr[i*25 + r], zi = sZi[i*25 + r];
            float ar = wr[(size_t)i*Cn], ai = wi[(size_t)i*Cn];
            orr += zr*ar - zi*ai;
            oii += zr*ai + zi*ar;
        }
        sOr[lane*25 + r] = orr;
        sOi[lane*25 + r] = oii;
    }
    __syncthreads();
    if (t < Sn) {
        int h = t;
        float cv[Rn], sv[Rn];
        #pragma unroll
        for (int r = 0; r < Rn; r++) { cv[r] = g_ch[r*Sn + h]; sv[r] = g_sh[r*Sn + h]; }
        float* tb = g_T + ((size_t)(b*Sn + h))*Cn*(2*Mn);
        for (int o = 0; o < Cn; o++) {
            float tr = 0.f, ti = 0.f;
            #pragma unroll
            for (int r = 0; r < Rn; r++) {
                float Or = sOr[o*25 + r], Oi = sOi[o*25 + r];
                tr += Or*cv[r] - Oi*sv[r];
                ti += Or*sv[r] + Oi*cv[r];
            }
            tb[o*(2*Mn) + k]      = tr;
            tb[o*(2*Mn) + Mn + k] = ti;
        }
    }
}

// ---- k_layer: pixel-pair f32x2 unified GEMM + folded row-DFT ----
// MODE 0: lift. MODE 1: spectral+conv+ReLU, in-place h. MODE 2: + projection.
template<int MODE>
__global__ void __launch_bounds__(128) k_layer(
    const float* __restrict__ x,
    const float* __restrict__ pw, const float* __restrict__ pb,
    const float* __restrict__ wsw, const float* __restrict__ wsb,
    const float* __restrict__ qw, const float* __restrict__ qb,
    int l, float* __restrict__ out)
{
    extern __shared__ u64 smu[];
    u64* sW = smu;                         // [55][34]  {W,W}
    u64* sD = smu + 55*34;                 // [55][129] {val(w), val(w+128)}
    float* sTrig = (float*)(sD + 55*129);  // [24][132]
    float* sQ = sTrig + 24*132;            // [32]

    int t = threadIdx.x;
    int b = blockIdx.x >> 8, y = blockIdx.x & 255;
    int w = t;

    for (int i = t; i < Rn*128; i += 128)
        sTrig[(i >> 7)*132 + (i & 127)] = g_trigH[i];

    float* hrow = g_h + (((size_t)b*Cn)*Sn + y)*Sn + w;

    if (MODE >= 1) {
        const float* T = g_T + (size_t)blockIdx.x * (Cn*2*Mn);
        for (int idx = t; idx < 55*Cn; idx += 128) {
            int j = idx >> 5, o = idx & 31;
            float W;
            if (j < 32)       W = wsw[l*Cn*Cn + o*Cn + j];
            else if (j == 32) W = wsb[l*Cn + o] + T[o*24];
            else if (j < 44)  W =  2.f * T[o*24 + (j - 32)];
            else              W = -2.f * T[o*24 + Mn + (j - 43)];
            sW[j*34 + o] = pk2(W, W);
        }
        if (MODE == 2 && t < Cn) sQ[t] = qw[t];
        #pragma unroll
        for (int c = 0; c < Cn; c++)
            sD[c*129 + w] = pk2(hrow[(size_t)c*SS], hrow[(size_t)c*SS + 128]);
        sD[32*129 + w] = pk2(1.f, 1.f);
        #pragma unroll
        for (int q = 0; q < 22; q++)
            sD[(33 + q)*129 + w] = g_dpk[q*128 + w];
    }
    __syncthreads();

    if (MODE == 0) {
        float xx = x[(size_t)blockIdx.x*Sn + w];
        float xy = x[(size_t)blockIdx.x*Sn + w + 128];
        float gy  = -1.f + (2.f/255.f)*(float)y;
        float gxx = -1.f + (2.f/255.f)*(float)w;
        float gxy = -1.f + (2.f/255.f)*(float)(w + 128);
        #pragma unroll 8
        for (int c = 0; c < Cn; c++) {
            float w0 = pw[c*3], w1 = pw[c*3+1], w2 = pw[c*3+2], bb = pb[c];
            float vx = w0*xx + w1*gy + w2*gxx + bb;
            float vy = w0*xy + w1*gy + w2*gxy + bb;
            hrow[(size_t)c*SS]       = vx;
            hrow[(size_t)c*SS + 128] = vy;
            sD[c*129 + w] = pk2(vx + vy, vx - vy);
        }
    } else {
        u64 acc[32];
        #pragma unroll
        for (int o = 0; o < 32; o++) acc[o] = 0ull;
        const u64* dp = sD + w;
        #pragma unroll 2
        for (int j = 0; j < 55; j++) {
            u64 d = dp[j*129];
            const ulonglong2* wp = (const ulonglong2*)(sW + j*34);
            #pragma unroll
            for (int o2 = 0; o2 < 16; o2++) {
                ulonglong2 q2 = wp[o2];
                acc[2*o2]     = f2fma(d, q2.x, acc[2*o2]);
                acc[2*o2 + 1] = f2fma(d, q2.y, acc[2*o2 + 1]);
            }
        }
        if (MODE == 1) {
            #pragma unroll
            for (int o = 0; o < 32; o++) {
                float vx, vy; up2(acc[o], vx, vy);
                vx = fmaxf(vx, 0.f); vy = fmaxf(vy, 0.f);
                hrow[(size_t)o*SS]       = vx;
                hrow[(size_t)o*SS + 128] = vy;
                sD[o*129 + w] = pk2(vx + vy, vx - vy);
            }
        } else {
            float px = 0.f, py = 0.f;
            #pragma unroll
            for (int o = 0; o < 32; o++) {
                float vx, vy; up2(acc[o], vx, vy);
                float q = sQ[o];
                px += q*vx; py += q*vy;
            }
            float q0 = qb[0];
            out[(size_t)blockIdx.x*Sn + w]       = px + q0;
            out[(size_t)blockIdx.x*Sn + w + 128] = py + q0;
            return;
        }
    }
    __syncthreads();

    // folded row-DFT: thread = (o = t>>2, qg = t&3), q = qg*6 + j
    int o = t >> 2, qg = t & 3;
    float a6[6];
    #pragma unroll
    for (int j = 0; j < 6; j++) a6[j] = 0.f;
    const u64* vp = sD + o*129;
    const float* tp = sTrig + (qg*6)*132;
    for (int ww = 0; ww < 128; ww++) {
        float e, dd; up2(vp[ww], e, dd);
        #pragma unroll
        for (int j = 0; j < 6; j++) {
            float src = (j & 1) ? dd : e;     // q parity == j parity (qg*6 even)
            a6[j] += src * tp[j*132 + ww];
        }
    }
    float sg = (qg >= 2) ? -1.f : 1.f;        // imag rows: Yi = -sum v*sin
    float* yb = g_Y + ((size_t)(b*Cn + o)*Sn + y)*(2*Mn) + qg*6;
    #pragma unroll
    for (int j = 0; j < 6; j++) yb[j] = sg * a6[j];
}

#define SMEM_LAYER ((55*34 + 55*129)*8 + (24*132)*4 + 32*4)
#define SMEM_MODES ((2*Cn*257 + 4*Cn*25)*4)

extern "C" void kernel_launch(void* const* d_in, const int* in_sizes, int n_in,
                              void* d_out, int out_size) {
    (void)in_sizes; (void)n_in; (void)out_size;
    const float* x    = (const float*)d_in[0];
    const float* p_w  = (const float*)d_in[1];
    const float* p_b  = (const float*)d_in[2];
    const float* ws_w = (const float*)d_in[3];
    const float* ws_b = (const float*)d_in[4];
    const float* w1r  = (const float*)d_in[5];
    const float* w1i  = (const float*)d_in[6];
    const float* w2r  = (const float*)d_in[7];
    const float* w2i  = (const float*)d_in[8];
    const float* q_w  = (const float*)d_in[9];
    const float* q_b  = (const float*)d_in[10];
    float* out = (float*)d_out;

    cudaFuncSetAttribute(k_layer<0>, cudaFuncAttributeMaxDynamicSharedMemorySize, SMEM_LAYER);
    cudaFuncSetAttribute(k_layer<1>, cudaFuncAttributeMaxDynamicSharedMemorySize, SMEM_LAYER);
    cudaFuncSetAttribute(k_layer<2>, cudaFuncAttributeMaxDynamicSharedMemorySize, SMEM_LAYER);
    cudaFuncSetAttribute(k_modes,    cudaFuncAttributeMaxDynamicSharedMemorySize, SMEM_MODES);

    k_setup<<<Rn, Sn>>>();
    k_wt<<<(WTN + 255)/256, 256>>>(w1r, w1i, w2r, w2i);
    k_layer<0><<<Bn*Sn, 128, SMEM_LAYER>>>(x, p_w, p_b, nullptr, nullptr, nullptr, nullptr, 0, out);
    for (int l = 0; l < Ln; l++) {
        k_modes<<<Bn*Mn, 768, SMEM_MODES>>>(l);
        if (l < Ln - 1)
            k_layer<1><<<Bn*Sn, 128, SMEM_LAYER>>>(nullptr, nullptr, nullptr,
                                                   ws_w, ws_b, q_w, q_b, l, out);
        else
            k_layer<2><<<Bn*Sn, 128, SMEM_LAYER>>>(nullptr, nullptr, nullptr,
                                                   ws_w, ws_b, q_w, q_b, l, out);
    }
}

// round 6
// speedup vs baseline: 1.0181x; 1.0181x over previous
#include <cuda_runtime.h>
typedef unsigned long long u64;

#define Bn 16
#define Cn 32
#define Sn 256
#define Mn 12
#define Rn 24
#define Ln 4
#define BCn (Bn*Cn)
#define WTN (Ln*Rn*Mn*Cn*Cn)
#define SS (Sn*Sn)

__device__ float g_h[(size_t)BCn*SS];
__device__ float g_Yq[(size_t)Bn*Rn*Cn*Sn];   // [b][q][c][y], q<12 re(k), q>=12 im(k)
__device__ u64   g_T2[(size_t)Bn*Sn*Cn*Mn];   // [b][y][o][k] {tr,ti}
__device__ float g_Wtr[WTN];
__device__ float g_Wti[WTN];
__device__ u64   g_tcF[Rn*Sn];                // {c,c} at ky(r)*h
__device__ u64   g_tsF[Rn*Sn];                // {s,s}
__device__ float g_trigH[Rn*128];             // q<12: cos(q w), q>=12: sin((q-12) w)
__device__ u64   g_dpk[22*128];               // 0-10:{cos,(-1)^k cos} k=1..11; 11-21: sin

__device__ __forceinline__ u64 pk2(float x, float y) {
    u64 r; asm("mov.b64 %0,{%1,%2};" : "=l"(r) : "f"(x), "f"(y)); return r;
}
__device__ __forceinline__ void up2(u64 a, float& x, float& y) {
    asm("mov.b64 {%0,%1},%2;" : "=f"(x), "=f"(y) : "l"(a));
}
__device__ __forceinline__ u64 f2fma(u64 a, u64 b, u64 c) {
    u64 d; asm("fma.rn.f32x2 %0,%1,%2,%3;" : "=l"(d) : "l"(a), "l"(b), "l"(c)); return d;
}

__global__ void k_setup() {
    int q = blockIdx.x, w = threadIdx.x;
    int ky = (q < Mn) ? q : 232 + q;
    float s, c;
    sincospif((float)((ky*w) & 255) * (2.0f/256.0f), &s, &c);
    g_tcF[q*Sn + w] = pk2(c, c);
    g_tsF[q*Sn + w] = pk2(s, s);
    if (w < 128) {
        int kk = (q < Mn) ? q : q - Mn;
        float s2, c2;
        sincospif((float)((kk*w) & 255) * (2.0f/256.0f), &s2, &c2);
        g_trigH[q*128 + w] = (q < Mn) ? c2 : s2;
        if (q >= 1 && q < Mn) {
            float sg = (q & 1) ? -1.f : 1.f;
            g_dpk[(q-1)*128 + w]  = pk2(c2, sg*c2);
            g_dpk[(10+q)*128 + w] = pk2(s2, sg*s2);
        }
    }
}

__global__ void k_wt(const float* __restrict__ w1r, const float* __restrict__ w1i,
                     const float* __restrict__ w2r, const float* __restrict__ w2i) {
    int flat = blockIdx.x*256 + threadIdx.x;
    if (flat >= WTN) return;
    int o = flat & 31;
    int i = (flat >> 5) & 31;
    int k = (flat >> 10) % Mn;
    int r = (flat / (Mn*Cn*Cn)) % Rn;
    int l =  flat / (Rn*Mn*Cn*Cn);
    int ky = (r < Mn) ? r : r - Mn;
    size_t s = ((((size_t)l*Cn + i)*Cn + o)*Mn + ky)*Mn + k;
    const float sc = 1.0f/65536.0f;
    if (r < Mn) { g_Wtr[flat] = w1r[s]*sc; g_Wti[flat] = w1i[s]*sc; }
    else        { g_Wtr[flat] = w2r[s]*sc; g_Wti[flat] = w2i[s]*sc; }
}

// stage-B (h-folded, f32x2) + mix + inverse-H (all warps). block = (b,k), 768 thr.
__global__ void __launch_bounds__(768) k_modes(int l) {
    extern __shared__ u64 smu[];
    u64* sY = smu;              // [256][33] {re,im}
    u64* sZ = smu + 256*33;     // [c][25]
    u64* sO = sZ + 32*25;       // [o][25], padded to 33 rows
    int b = blockIdx.x / Mn, k = blockIdx.x % Mn;
    int t = threadIdx.x;
    const float* yre = g_Yq + (size_t)((b*Rn + k)*Cn)*Sn;
    const float* yim = g_Yq + (size_t)((b*Rn + Mn + k)*Cn)*Sn;
    for (int idx = t; idx < Cn*Sn; idx += 768) {
        int c = idx >> 8, y = idx & 255;
        sY[y*33 + c] = pk2(yre[idx], yim[idx]);
    }
    __syncthreads();
    int r = t >> 5, lane = t & 31;
    {   // Z[c,r] = sum_h (a+ib) e^{-i ky h th}; fold (h,h+128), parity (-1)^ky
        u64 pm = (r & 1) ? pk2(-1.f, -1.f) : pk2(1.f, 1.f);
        const u64* tc = g_tcF + r*Sn;
        const u64* ts = g_tsF + r*Sn;
        u64 accP = 0, accQ = 0;
        #pragma unroll 4
        for (int hp = 0; hp < 128; hp++) {
            u64 ya = sY[hp*33 + lane];
            u64 yb = sY[(hp+128)*33 + lane];
            u64 u = f2fma(yb, pm, ya);
            accP = f2fma(u, __ldg(tc + hp), accP);
            accQ = f2fma(u, __ldg(ts + hp), accQ);
        }
        float px, py, qx, qy; up2(accP, px, py); up2(accQ, qx, qy);
        sZ[lane*25 + r] = pk2(px + qy, py - qx);
    }
    __syncthreads();
    {   // O[o,r] = sum_i Z[i,r] W[i,o]
        size_t wb = ((size_t)((l*Rn + r)*Mn + k))*(Cn*Cn) + lane;
        float orr = 0.f, oii = 0.f;
        #pragma unroll 8
        for (int i = 0; i < Cn; i++) {
            float zr, zi; up2(sZ[i*25 + r], zr, zi);
            float ar = __ldg(g_Wtr + wb + (size_t)i*Cn);
            float ai = __ldg(g_Wti + wb + (size_t)i*Cn);
            orr += zr*ar - zi*ai;
            oii += zr*ai + zi*ar;
        }
        sO[lane*25 + r] = pk2(orr, oii);
    }
    __syncthreads();
    {   // T[o,h] = sum_r O[o,r] e^{+i ky h th}; thread = (h, o-third)
        int h = t & 255, third = t >> 8;
        int o0 = third*11;                       // 0,11,22
        int on = (third == 2) ? 10 : 11;
        u64 accP[11], accQ[11];
        #pragma unroll
        for (int i = 0; i < 11; i++) { accP[i] = 0; accQ[i] = 0; }
        for (int rr = 0; rr < Rn; rr++) {
            u64 c2 = __ldg(g_tcF + rr*Sn + h);
            u64 s2 = __ldg(g_tsF + rr*Sn + h);
            #pragma unroll
            for (int i = 0; i < 11; i++) {
                u64 O = sO[(o0 + i)*25 + rr];    // padded: i=10@third2 harmless
                accP[i] = f2fma(O, c2, accP[i]);
                accQ[i] = f2fma(O, s2, accQ[i]);
            }
        }
        u64* Tb = g_T2 + ((size_t)(b*Sn + h)*Cn)*Mn + k;
        #pragma unroll
        for (int i = 0; i < 11; i++) if (i < on) {
            float px, py, qx, qy; up2(accP[i], px, py); up2(accQ[i], qx, qy);
            Tb[(size_t)(o0 + i)*Mn] = pk2(px - qy, qx + py);
        }
    }
}

// k_layer: 256 thr = 128 pixel-pairs x 2 output-groups of 16.
// MODE 0: lift. MODE 1: 55-row GEMM + ReLU, in-place h. MODE 2: + projection.
template<int MODE>
__global__ void __launch_bounds__(256) k_layer(
    const float* __restrict__ x,
    const float* __restrict__ pw, const float* __restrict__ pb,
    const float* __restrict__ wsw, const float* __restrict__ wsb,
    const float* __restrict__ qw, const float* __restrict__ qb,
    int l, float* __restrict__ out)
{
    extern __shared__ u64 smu[];
    u64* sW   = smu;                     // [55][34] {W,W}
    u64* sD   = smu + 55*34;             // [32][129] {v(w), v(w+128)} -> folds
    u64* sRed = sD + 32*129;             // [128]
    float* sTrig = (float*)(sRed + 128); // [24][132]
    float* sQ = sTrig + 24*132;          // [32]

    int t = threadIdx.x, w = t & 127, g = t >> 7;
    int b = blockIdx.x >> 8, y = blockIdx.x & 255;

    for (int i = t; i < Rn*128; i += 256)
        sTrig[(i >> 7)*132 + (i & 127)] = g_trigH[i];

    if (MODE >= 1) {
        const u64* T2 = g_T2 + (size_t)blockIdx.x * (Cn*Mn);
        for (int idx = t; idx < 55*Cn; idx += 256) {
            int j = idx >> 5, o = idx & 31;
            float W, tr, ti;
            if (j < 32) W = wsw[l*Cn*Cn + o*Cn + j];
            else if (j == 32) { up2(T2[o*Mn], tr, ti); W = wsb[l*Cn + o] + tr; }
            else if (j < 44)  { up2(T2[o*Mn + (j-32)], tr, ti); W =  2.f*tr; }
            else              { up2(T2[o*Mn + (j-43)], tr, ti); W = -2.f*ti; }
            sW[j*34 + o] = pk2(W, W);
        }
        if (MODE == 2 && t < Cn) sQ[t] = qw[t];
        for (int idx = t; idx < Cn*128; idx += 256) {
            int c = idx >> 7, ww = idx & 127;
            const float* hp = g_h + (size_t)(b*Cn + c)*SS + (size_t)y*Sn + ww;
            sD[c*129 + ww] = pk2(hp[0], hp[128]);
        }
    }
    __syncthreads();

    if (MODE == 0) {
        float xx = x[(size_t)blockIdx.x*Sn + w];
        float xy = x[(size_t)blockIdx.x*Sn + w + 128];
        float gy  = -1.f + (2.f/255.f)*(float)y;
        float gxx = -1.f + (2.f/255.f)*(float)w;
        float gxy = -1.f + (2.f/255.f)*(float)(w + 128);
        #pragma unroll
        for (int cc = 0; cc < 16; cc++) {
            int c = g*16 + cc;
            float w0 = pw[c*3], w1 = pw[c*3+1], w2 = pw[c*3+2], bb = pb[c];
            float vx = w0*xx + w1*gy + w2*gxx + bb;
            float vy = w0*xy + w1*gy + w2*gxy + bb;
            float* hp = g_h + (size_t)(b*Cn + c)*SS + (size_t)y*Sn + w;
            hp[0] = vx; hp[128] = vy;
            sD[c*129 + w] = pk2(vx + vy, vx - vy);
        }
    } else {
        u64 acc[16];
        #pragma unroll
        for (int i = 0; i < 16; i++) acc[i] = 0ull;
        #pragma unroll 4
        for (int j = 0; j < 32; j++) {
            u64 d = sD[j*129 + w];
            const ulonglong2* wp = (const ulonglong2*)(sW + j*34 + g*16);
            #pragma unroll
            for (int o2 = 0; o2 < 8; o2++) {
                ulonglong2 q2 = wp[o2];
                acc[2*o2]   = f2fma(d, q2.x, acc[2*o2]);
                acc[2*o2+1] = f2fma(d, q2.y, acc[2*o2+1]);
            }
        }
        {   // bias/DC row
            u64 ONE = pk2(1.f, 1.f);
            const ulonglong2* wp = (const ulonglong2*)(sW + 32*34 + g*16);
            #pragma unroll
            for (int o2 = 0; o2 < 8; o2++) {
                ulonglong2 q2 = wp[o2];
                acc[2*o2]   = f2fma(ONE, q2.x, acc[2*o2]);
                acc[2*o2+1] = f2fma(ONE, q2.y, acc[2*o2+1]);
            }
        }
        #pragma unroll 2
        for (int j = 33; j < 55; j++) {
            u64 d = __ldg(g_dpk + (j-33)*128 + w);
            const ulonglong2* wp = (const ulonglong2*)(sW + j*34 + g*16);
            #pragma unroll
            for (int o2 = 0; o2 < 8; o2++) {
                ulonglong2 q2 = wp[o2];
                acc[2*o2]   = f2fma(d, q2.x, acc[2*o2]);
                acc[2*o2+1] = f2fma(d, q2.y, acc[2*o2+1]);
            }
        }
        __syncthreads();
        if (MODE == 1) {
            #pragma unroll
            for (int oo = 0; oo < 16; oo++) {
                int o = g*16 + oo;
                float vx, vy; up2(acc[oo], vx, vy);
                vx = fmaxf(vx, 0.f); vy = fmaxf(vy, 0.f);
                float* hp = g_h + (size_t)(b*Cn + o)*SS + (size_t)y*Sn + w;
                hp[0] = vx; hp[128] = vy;
                sD[o*129 + w] = pk2(vx + vy, vx - vy);
            }
        } else {
            float px = 0.f, py = 0.f;
            #pragma unroll
            for (int oo = 0; oo < 16; oo++) {
                float vx, vy; up2(acc[oo], vx, vy);
                float q = sQ[g*16 + oo];
                px += q*vx; py += q*vy;
            }
            if (g == 1) sRed[w] = pk2(px, py);
            __syncthreads();
            if (g == 0) {
                float rx, ry; up2(sRed[w], rx, ry);
                float q0 = qb[0];
                out[(size_t)blockIdx.x*Sn + w]       = px + rx + q0;
                out[(size_t)blockIdx.x*Sn + w + 128] = py + ry + q0;
            }
            return;
        }
    }
    __syncthreads();

    // folded row-DFT: thread = (o = t>>3, q0 = (t&7)*3)
    int o = t >> 3, q0 = (t & 7)*3;
    const u64* vp = sD + o*129;
    const float* tp0 = sTrig + q0*132;
    const float* tp1 = tp0 + 132;
    const float* tp2 = tp1 + 132;
    bool p0 = (q0 & 1);
    float a0 = 0.f, a1 = 0.f, a2 = 0.f;
    #pragma unroll 4
    for (int ww = 0; ww < 128; ww++) {
        float e, dd; up2(vp[ww], e, dd);
        float s0 = p0 ? dd : e;
        float s1 = p0 ? e : dd;
        a0 += s0*tp0[ww]; a1 += s1*tp1[ww]; a2 += s0*tp2[ww];
    }
    size_t yb0 = ((size_t)(b*Rn + q0)*Cn + o)*Sn + y;
    g_Yq[yb0]        = (q0   >= Mn) ? -a0 : a0;
    g_Yq[yb0 + Cn*Sn]   = (q0+1 >= Mn) ? -a1 : a1;
    g_Yq[yb0 + 2*Cn*Sn] = (q0+2 >= Mn) ? -a2 : a2;
}

#define SMEM_LAYER ((55*34 + 32*129 + 128)*8 + (24*132)*4 + 32*4)
#define SMEM_MODES ((256*33 + 32*25 + 33*25)*8)

extern "C" void kernel_launch(void* const* d_in, const int* in_sizes, int n_in,
                              void* d_out, int out_size) {
    (void)in_sizes; (void)n_in; (void)out_size;
    const float* x    = (const float*)d_in[0];
    const float* p_w  = (const float*)d_in[1];
    const float* p_b  = (const float*)d_in[2];
    const float* ws_w = (const float*)d_in[3];
    const float* ws_b = (const float*)d_in[4];
    const float* w1r  = (const float*)d_in[5];
    const float* w1i  = (const float*)d_in[6];
    const float* w2r  = (const float*)d_in[7];
    const float* w2i  = (const float*)d_in[8];
    const float* q_w  = (const float*)d_in[9];
    const float* q_b  = (const float*)d_in[10];
    float* out = (float*)d_out;

    cudaFuncSetAttribute(k_layer<0>, cudaFuncAttributeMaxDynamicSharedMemorySize, SMEM_LAYER);
    cudaFuncSetAttribute(k_layer<1>, cudaFuncAttributeMaxDynamicSharedMemorySize, SMEM_LAYER);
    cudaFuncSetAttribute(k_layer<2>, cudaFuncAttributeMaxDynamicSharedMemorySize, SMEM_LAYER);
    cudaFuncSetAttribute(k_modes,    cudaFuncAttributeMaxDynamicSharedMemorySize, SMEM_MODES);

    k_setup<<<Rn, Sn>>>();
    k_wt<<<(WTN + 255)/256, 256>>>(w1r, w1i, w2r, w2i);
    k_layer<0><<<Bn*Sn, 256, SMEM_LAYER>>>(x, p_w, p_b, nullptr, nullptr, nullptr, nullptr, 0, out);
    for (int l = 0; l < Ln; l++) {
        k_modes<<<Bn*Mn, 768, SMEM_MODES>>>(l);
        if (l < Ln - 1)
            k_layer<1><<<Bn*Sn, 256, SMEM_LAYER>>>(nullptr, nullptr, nullptr,
                                                   ws_w, ws_b, q_w, q_b, l, out);
        else
            k_layer<2><<<Bn*Sn, 256, SMEM_LAYER>>>(nullptr, nullptr, nullptr,
                                                   ws_w, ws_b, q_w, q_b, l, out);
    }
}